// round 12
// baseline (speedup 1.0000x reference)
#include <cuda_runtime.h>
#include <cuda_fp16.h>
#include <cstdint>

#define B_  1024
#define D_  512
#define V_  100000
#define VN  391   // number of 256-wide vocab slices

constexpr float MARGIN_COS = 0.9210609940028851f;  // cos(0.4)
constexpr float MARGIN_SIN = 0.3894183423086505f;  // sin(0.4)
constexpr float EPS_CLIP   = 1e-7f;

// ---- scratch (device globals: allocation-free per harness rules) ----
__device__ __align__(128) __half g_x16[B_ * D_];
__device__ __align__(128) __half g_w16[(size_t)D_ * V_];
__device__ float g_inv_x[B_];
__device__ float g_inv_w[V_];
__device__ float g_sumexp[B_];
__device__ float g_label_logit[B_];
__device__ int   g_labels[B_];
__device__ int   g_wclaim[VN];
__device__ int   g_wdone[VN];

// ============================================================
// labels dtype detection + zero the claim/done flags each run
// ============================================================
__global__ void k_labels(const int* __restrict__ raw) {
    __shared__ int nonzero;
    int t = threadIdx.x;  // 1024
    if (t == 0) nonzero = 0;
    __syncthreads();
    if (t < 512) {
        if (raw[2 * t + 1] != 0) atomicOr(&nonzero, 1);
    }
    if (t < VN) { g_wclaim[t] = 0; g_wdone[t] = 0; }
    __syncthreads();
    bool is64 = (nonzero == 0);
    g_labels[t] = is64 ? raw[2 * t] : raw[t];
}

// ============================================================
// x prep: fp16 convert + row inv-norms; zero g_sumexp
// ============================================================
__global__ void k_prep_x(const float* __restrict__ x) {
    int b = blockIdx.x;
    int t = threadIdx.x;  // 128
    float ss = 0.f;
#pragma unroll
    for (int i = 0; i < 4; i++) {
        int k = t + i * 128;
        float v = x[b * D_ + k];
        ss += v * v;
        g_x16[b * D_ + k] = __float2half(v);
    }
#pragma unroll
    for (int o = 16; o; o >>= 1) ss += __shfl_xor_sync(0xffffffffu, ss, o);
    __shared__ float ws[4];
    if ((t & 31) == 0) ws[t >> 5] = ss;
    __syncthreads();
    if (t == 0) {
        float s = ws[0] + ws[1] + ws[2] + ws[3];
        g_inv_x[b]  = 1.0f / fmaxf(sqrtf(s), 1e-12f);
        g_sumexp[b] = 0.f;
    }
}

// ============================================================
// GEMM + fused ArcFace epilogue  (fp16 in, fp16 accum)
// W fp32->fp16 conversion folded in: first CTA of each bn group
// claims the slice, converts + computes inv_w; siblings spin.
// CTA: BM=128 x BN=256, BK=32, 512 threads (2x8 warps, 64x32/warp)
// ============================================================
#define BM 128
#define BN 256
#define BK 32
#define STAGES 3
#define A_PITCH 40    // 32 + 8 pad (80B rows; conflict-free ldmatrix)
#define B_PITCH 264   // 256 + 8 pad (528B rows; 528 mod 128 = 16 -> conflict-free)
#define A_STAGE (BM * A_PITCH)          // halves = 5120
#define B_STAGE (BK * B_PITCH)          // 8448
#define SMEM_DYN ((A_STAGE + B_STAGE) * STAGES * 2)  // 81408 bytes

__device__ __forceinline__ void cp_async16(uint32_t smem, const void* gmem, int sz) {
    asm volatile("cp.async.cg.shared.global [%0], [%1], 16, %2;\n"
                 :: "r"(smem), "l"(gmem), "r"(sz) : "memory");
}
__device__ __forceinline__ void ldsm_x4(uint32_t& r0, uint32_t& r1, uint32_t& r2, uint32_t& r3, uint32_t addr) {
    asm volatile("ldmatrix.sync.aligned.m8n8.x4.shared.b16 {%0,%1,%2,%3}, [%4];\n"
                 : "=r"(r0), "=r"(r1), "=r"(r2), "=r"(r3) : "r"(addr));
}
__device__ __forceinline__ void ldsm_x4_t(uint32_t& r0, uint32_t& r1, uint32_t& r2, uint32_t& r3, uint32_t addr) {
    asm volatile("ldmatrix.sync.aligned.m8n8.x4.trans.shared.b16 {%0,%1,%2,%3}, [%4];\n"
                 : "=r"(r0), "=r"(r1), "=r"(r2), "=r"(r3) : "r"(addr));
}
__device__ __forceinline__ void mma16816_f16(uint32_t* c, const uint32_t* a, const uint32_t* b) {
    asm volatile(
        "mma.sync.aligned.m16n8k16.row.col.f16.f16.f16.f16 "
        "{%0,%1}, {%2,%3,%4,%5}, {%6,%7}, {%0,%1};\n"
        : "+r"(c[0]), "+r"(c[1])
        : "r"(a[0]), "r"(a[1]), "r"(a[2]), "r"(a[3]), "r"(b[0]), "r"(b[1]));
}

__global__ __launch_bounds__(512, 2) void k_gemm(const float* __restrict__ w) {
    extern __shared__ __half smem_dyn[];
    __half* As = smem_dyn;                       // STAGES * A_STAGE
    __half* Bs = smem_dyn + STAGES * A_STAGE;    // STAGES * B_STAGE
    __shared__ float rowsum_sm[BM];
    __shared__ float inv_x_s[BM];
    __shared__ float inv_w_s[BN];
    __shared__ int   label_s[BM];
    __shared__ float cvt_red[256];
    __shared__ int   s_claim;

    const int bm = blockIdx.x;   // M-tile (fast index -> bn group contiguous)
    const int bn = blockIdx.y;   // V-slice
    const int tid = threadIdx.x;
    const int warp = tid >> 5, lane = tid & 31;
    const int wm = warp & 1;     // 2 warps over M (64 rows each)
    const int wn = warp >> 1;    // 8 warps over N (32 cols each)

    // ---- W slice conversion: first arriver claims, others spin ----
    if (tid == 0) s_claim = (atomicCAS(&g_wclaim[bn], 0, 1) == 0) ? 1 : 0;
    __syncthreads();
    if (s_claim) {
        int c = tid & 255, dh = tid >> 8;       // 2 threads per column
        int v = bn * BN + c;
        float ss = 0.f;
        if (v < V_) {
#pragma unroll 4
            for (int i = 0; i < 256; i++) {
                int d = dh * 256 + i;
                size_t idx = (size_t)d * V_ + v;
                float val = w[idx];
                ss += val * val;
                g_w16[idx] = __float2half(val);
            }
        }
        if (dh) cvt_red[c] = ss;
        __syncthreads();
        if (!dh) {
            ss += cvt_red[c];
            if (v < V_) g_inv_w[v] = 1.0f / fmaxf(sqrtf(ss), 1e-12f);
        }
        __threadfence();
        __syncthreads();
        if (tid == 0) atomicExch(&g_wdone[bn], 1);
    } else {
        if (tid == 0) {
            while (atomicAdd(&g_wdone[bn], 0) == 0) __nanosleep(64);
        }
        __syncthreads();
        __threadfence();
    }

    const uint32_t as0 = (uint32_t)__cvta_generic_to_shared(As);
    const uint32_t bs0 = (uint32_t)__cvta_generic_to_shared(Bs);

    // 512 threads: A 8KB -> 1 cp16/thread; B 16KB -> 2 cp16/thread
    auto load_tiles = [&](int kt, int buf) {
        {
            int row  = tid >> 2;             // 0..127
            int koff = (tid & 3) * 8;        // 0,8,16,24
            const __half* gp = &g_x16[(bm * BM + row) * D_ + kt * BK + koff];
            cp_async16(as0 + (buf * A_STAGE + row * A_PITCH + koff) * 2, gp, 16);
        }
#pragma unroll
        for (int i = 0; i < 2; i++) {
            int c = tid + i * 512;           // 0..1023
            int drow = c >> 5;               // 0..31
            int voff = (c & 31) * 8;         // 0..248
            int v = bn * BN + voff;
            const __half* gp = &g_w16[(size_t)(kt * BK + drow) * V_ + v];
            cp_async16(bs0 + (buf * B_STAGE + drow * B_PITCH + voff) * 2, gp, (v < V_) ? 16 : 0);
        }
        asm volatile("cp.async.commit_group;\n" ::: "memory");
    };

    load_tiles(0, 0);
    load_tiles(1, 1);

    if (tid < BM) {
        inv_x_s[tid]   = g_inv_x[bm * BM + tid];
        label_s[tid]   = g_labels[bm * BM + tid];
        rowsum_sm[tid] = 0.f;
    }
    if (tid < BN) {
        int v = bn * BN + tid;
        inv_w_s[tid]   = (v < V_) ? g_inv_w[v] : 0.f;
    }

    uint32_t acc[4][4][2];  // fp16 accumulators (half2 pairs)
#pragma unroll
    for (int mf = 0; mf < 4; mf++)
#pragma unroll
        for (int nf = 0; nf < 4; nf++) {
            acc[mf][nf][0] = 0u;
            acc[mf][nf][1] = 0u;
        }

    const int KT = D_ / BK;  // 16
    for (int kt = 0; kt < KT; kt++) {
        asm volatile("cp.async.wait_group 1;\n" ::: "memory");
        __syncthreads();
        if (kt + 2 < KT) load_tiles(kt + 2, (kt + 2) % STAGES);
        else asm volatile("cp.async.commit_group;\n" ::: "memory");  // keep group count uniform

        int buf = kt % STAGES;
        uint32_t abase = as0 + buf * (A_STAGE * 2);
        uint32_t bbase = bs0 + buf * (B_STAGE * 2);

#pragma unroll
        for (int ks = 0; ks < 2; ks++) {
            uint32_t a[4][4];
#pragma unroll
            for (int mf = 0; mf < 4; mf++) {
                int row = wm * 64 + mf * 16 + (lane & 15);
                int col = ks * 16 + (lane >> 4) * 8;
                ldsm_x4(a[mf][0], a[mf][1], a[mf][2], a[mf][3],
                        abase + (row * A_PITCH + col) * 2);
            }
            uint32_t b[4][2];
#pragma unroll
            for (int ng = 0; ng < 2; ng++) {
                int krow = ks * 16 + (lane & 15);
                int ncol = wn * 32 + ng * 16 + (lane >> 4) * 8;
                uint32_t r0, r1, r2, r3;
                ldsm_x4_t(r0, r1, r2, r3, bbase + (krow * B_PITCH + ncol) * 2);
                b[ng * 2][0] = r0;      b[ng * 2][1] = r1;
                b[ng * 2 + 1][0] = r2;  b[ng * 2 + 1][1] = r3;
            }
#pragma unroll
            for (int mf = 0; mf < 4; mf++)
#pragma unroll
                for (int nf = 0; nf < 4; nf++)
                    mma16816_f16(acc[mf][nf], a[mf], b[nf]);
        }
    }
    __syncthreads();  // all compute done; rowsum_sm zeros visible

    // ---- fused ArcFace epilogue ----
#pragma unroll
    for (int mf = 0; mf < 4; mf++) {
        float rs0 = 0.f, rs1 = 0.f;
        int r0 = wm * 64 + mf * 16 + (lane >> 2);
        int r1 = r0 + 8;
#pragma unroll
        for (int nf = 0; nf < 4; nf++) {
            int cbase = wn * 32 + nf * 8 + (lane & 3) * 2;
            float2 v0 = __half22float2(*reinterpret_cast<__half2*>(&acc[mf][nf][0]));  // row r0
            float2 v1 = __half22float2(*reinterpret_cast<__half2*>(&acc[mf][nf][1]));  // row r1
            float d0[2] = {v0.x, v0.y};
            float d1[2] = {v1.x, v1.y};
#pragma unroll
            for (int j = 0; j < 2; j++) {
                int cc = cbase + j;
                int v = bn * BN + cc;
                if (v < V_) {
                    {
                        float cv = d0[j] * inv_x_s[r0] * inv_w_s[cc];
                        cv = fminf(fmaxf(cv, -1.f + EPS_CLIP), 1.f - EPS_CLIP);
                        float lg;
                        if (label_s[r0] == v) {
                            float s = sqrtf(fmaxf(1.f - cv * cv, 0.f));
                            lg = cv * MARGIN_COS - s * MARGIN_SIN;
                            g_label_logit[bm * BM + r0] = lg;
                        } else lg = cv;
                        rs0 += __expf(lg);
                    }
                    {
                        float cv = d1[j] * inv_x_s[r1] * inv_w_s[cc];
                        cv = fminf(fmaxf(cv, -1.f + EPS_CLIP), 1.f - EPS_CLIP);
                        float lg;
                        if (label_s[r1] == v) {
                            float s = sqrtf(fmaxf(1.f - cv * cv, 0.f));
                            lg = cv * MARGIN_COS - s * MARGIN_SIN;
                            g_label_logit[bm * BM + r1] = lg;
                        } else lg = cv;
                        rs1 += __expf(lg);
                    }
                }
            }
        }
        rs0 += __shfl_xor_sync(0xffffffffu, rs0, 1);
        rs0 += __shfl_xor_sync(0xffffffffu, rs0, 2);
        rs1 += __shfl_xor_sync(0xffffffffu, rs1, 1);
        rs1 += __shfl_xor_sync(0xffffffffu, rs1, 2);
        if ((lane & 3) == 0) {
            atomicAdd(&rowsum_sm[r0], rs0);
            atomicAdd(&rowsum_sm[r1], rs1);
        }
    }
    __syncthreads();
    if (tid < BM) atomicAdd(&g_sumexp[bm * BM + tid], rowsum_sm[tid]);
}

// ============================================================
// final: loss = mean_b( log(sumexp[b]) - label_logit[b] )
// ============================================================
__global__ void k_final(float* __restrict__ out) {
    int t = threadIdx.x;  // 1024
    float v = logf(g_sumexp[t]) - g_label_logit[t];
#pragma unroll
    for (int o = 16; o; o >>= 1) v += __shfl_xor_sync(0xffffffffu, v, o);
    __shared__ float ws[32];
    if ((t & 31) == 0) ws[t >> 5] = v;
    __syncthreads();
    if (t < 32) {
        float s = ws[t];
#pragma unroll
        for (int o = 16; o; o >>= 1) s += __shfl_xor_sync(0xffffffffu, s, o);
        if (t == 0) out[0] = s * (1.0f / (float)B_);
    }
}

// ============================================================
extern "C" void kernel_launch(void* const* d_in, const int* in_sizes, int n_in,
                              void* d_out, int out_size) {
    const float* x = (const float*)d_in[0];
    const float* w = (const float*)d_in[1];
    const int*   labels_raw = (const int*)d_in[2];
    float* out = (float*)d_out;

    static bool attr_set = false;
    if (!attr_set) {
        cudaFuncSetAttribute(k_gemm, cudaFuncAttributeMaxDynamicSharedMemorySize, SMEM_DYN);
        attr_set = true;
    }

    k_labels<<<1, 1024>>>(labels_raw);
    k_prep_x<<<B_, 128>>>(x);
    dim3 grid(B_ / BM, (V_ + BN - 1) / BN);  // (8, 391)
    k_gemm<<<grid, 512, SMEM_DYN>>>(w);
    k_final<<<1, 1024>>>(out);
}

// round 13
// speedup vs baseline: 1.5474x; 1.5474x over previous
#include <cuda_runtime.h>
#include <cuda_fp16.h>
#include <cstdint>

#define B_  1024
#define D_  512
#define V_  100000

constexpr float MARGIN_COS = 0.9210609940028851f;  // cos(0.4)
constexpr float MARGIN_SIN = 0.3894183423086505f;  // sin(0.4)
constexpr float EPS_CLIP   = 1e-7f;

// ---- scratch (device globals: allocation-free per harness rules) ----
__device__ __align__(128) __half g_x16[B_ * D_];
__device__ __align__(128) __half g_w16[(size_t)D_ * V_];
__device__ float g_inv_x[B_];
__device__ float g_inv_w[V_];
__device__ float g_sumexp[B_];
__device__ float g_label_logit[B_];
__device__ int   g_labels[B_];

// ============================================================
// labels dtype detection (int64 vs int32) + normalization
// ============================================================
__global__ void k_labels(const int* __restrict__ raw) {
    __shared__ int nonzero;
    int t = threadIdx.x;  // 1024
    if (t == 0) nonzero = 0;
    __syncthreads();
    if (t < 512) {
        if (raw[2 * t + 1] != 0) atomicOr(&nonzero, 1);
    }
    __syncthreads();
    bool is64 = (nonzero == 0);
    g_labels[t] = is64 ? raw[2 * t] : raw[t];
}

// ============================================================
// x prep: fp16 convert + row inv-norms; zero g_sumexp
// ============================================================
__global__ void k_prep_x(const float* __restrict__ x) {
    int b = blockIdx.x;
    int t = threadIdx.x;  // 128
    float ss = 0.f;
#pragma unroll
    for (int i = 0; i < 4; i++) {
        int k = t + i * 128;
        float v = x[b * D_ + k];
        ss += v * v;
        g_x16[b * D_ + k] = __float2half(v);
    }
#pragma unroll
    for (int o = 16; o; o >>= 1) ss += __shfl_xor_sync(0xffffffffu, ss, o);
    __shared__ float ws[4];
    if ((t & 31) == 0) ws[t >> 5] = ss;
    __syncthreads();
    if (t == 0) {
        float s = ws[0] + ws[1] + ws[2] + ws[3];
        g_inv_x[b]  = 1.0f / fmaxf(sqrtf(s), 1e-12f);
        g_sumexp[b] = 0.f;
    }
}

// ============================================================
// w prep (chunked): fp16 convert + column inv-norms for v in [vlo, vhi)
// ============================================================
__global__ void k_prep_w(const float* __restrict__ w, int vlo, int vhi) {
    int v = vlo + blockIdx.x * 256 + threadIdx.x;
    if (v >= vhi) return;
    float ss = 0.f;
    size_t idx = (size_t)v;
#pragma unroll 8
    for (int d = 0; d < D_; d++) {
        float val = w[idx];
        ss += val * val;
        g_w16[idx] = __float2half(val);
        idx += V_;
    }
    g_inv_w[v] = 1.0f / fmaxf(sqrtf(ss), 1e-12f);
}

// ============================================================
// GEMM + fused ArcFace epilogue  (fp16 inputs, fp16 accum)
// CTA: BM=128 x BN=256, BK=32, 512 threads (2x8 warp grid, 64x32/warp)
// 2 CTAs/SM; 3-stage cp.async ring; mma.sync m16n8k16 f16
// ============================================================
#define BM 128
#define BN 256
#define BK 32
#define STAGES 3
#define A_PITCH 40    // 32 + 8 pad (80B rows; conflict-free ldmatrix)
#define B_PITCH 264   // 256 + 8 pad (528B rows; 528 mod 128 = 16 -> conflict-free)
#define A_STAGE (BM * A_PITCH)          // halves = 5120
#define B_STAGE (BK * B_PITCH)          // 8448
#define SMEM_DYN ((A_STAGE + B_STAGE) * STAGES * 2)  // 81408 bytes

__device__ __forceinline__ void cp_async16(uint32_t smem, const void* gmem, int sz) {
    asm volatile("cp.async.cg.shared.global [%0], [%1], 16, %2;\n"
                 :: "r"(smem), "l"(gmem), "r"(sz) : "memory");
}
__device__ __forceinline__ void ldsm_x4(uint32_t& r0, uint32_t& r1, uint32_t& r2, uint32_t& r3, uint32_t addr) {
    asm volatile("ldmatrix.sync.aligned.m8n8.x4.shared.b16 {%0,%1,%2,%3}, [%4];\n"
                 : "=r"(r0), "=r"(r1), "=r"(r2), "=r"(r3) : "r"(addr));
}
__device__ __forceinline__ void ldsm_x4_t(uint32_t& r0, uint32_t& r1, uint32_t& r2, uint32_t& r3, uint32_t addr) {
    asm volatile("ldmatrix.sync.aligned.m8n8.x4.trans.shared.b16 {%0,%1,%2,%3}, [%4];\n"
                 : "=r"(r0), "=r"(r1), "=r"(r2), "=r"(r3) : "r"(addr));
}
__device__ __forceinline__ void mma16816_f16(uint32_t* c, const uint32_t* a, const uint32_t* b) {
    asm volatile(
        "mma.sync.aligned.m16n8k16.row.col.f16.f16.f16.f16 "
        "{%0,%1}, {%2,%3,%4,%5}, {%6,%7}, {%0,%1};\n"
        : "+r"(c[0]), "+r"(c[1])
        : "r"(a[0]), "r"(a[1]), "r"(a[2]), "r"(a[3]), "r"(b[0]), "r"(b[1]));
}

__global__ __launch_bounds__(512, 2) void k_gemm(int bn0) {
    extern __shared__ __half smem_dyn[];
    __half* As = smem_dyn;                       // STAGES * A_STAGE
    __half* Bs = smem_dyn + STAGES * A_STAGE;    // STAGES * B_STAGE
    __shared__ float rowsum_sm[BM];
    __shared__ float inv_x_s[BM];
    __shared__ float inv_w_s[BN];
    __shared__ int   label_s[BM];

    const int bm = blockIdx.x;          // M-tile (fast index -> same-w CTAs adjacent)
    const int bn = blockIdx.y + bn0;    // V-slice (chunk offset)
    const int tid = threadIdx.x;
    const int warp = tid >> 5, lane = tid & 31;
    const int wm = warp & 1;     // 2 warps over M (64 rows each)
    const int wn = warp >> 1;    // 8 warps over N (32 cols each)

    const uint32_t as0 = (uint32_t)__cvta_generic_to_shared(As);
    const uint32_t bs0 = (uint32_t)__cvta_generic_to_shared(Bs);

    // 512 threads: A 8KB -> 1 cp16/thread; B 16KB -> 2 cp16/thread
    auto load_tiles = [&](int kt, int buf) {
        {
            int row  = tid >> 2;             // 0..127
            int koff = (tid & 3) * 8;        // 0,8,16,24
            const __half* gp = &g_x16[(bm * BM + row) * D_ + kt * BK + koff];
            cp_async16(as0 + (buf * A_STAGE + row * A_PITCH + koff) * 2, gp, 16);
        }
#pragma unroll
        for (int i = 0; i < 2; i++) {
            int c = tid + i * 512;           // 0..1023
            int drow = c >> 5;               // 0..31
            int voff = (c & 31) * 8;         // 0..248
            int v = bn * BN + voff;
            const __half* gp = &g_w16[(size_t)(kt * BK + drow) * V_ + v];
            cp_async16(bs0 + (buf * B_STAGE + drow * B_PITCH + voff) * 2, gp, (v < V_) ? 16 : 0);
        }
        asm volatile("cp.async.commit_group;\n" ::: "memory");
    };

    load_tiles(0, 0);
    load_tiles(1, 1);

    if (tid < BM) {
        inv_x_s[tid]   = g_inv_x[bm * BM + tid];
        label_s[tid]   = g_labels[bm * BM + tid];
        rowsum_sm[tid] = 0.f;
    }
    if (tid < BN) {
        int v = bn * BN + tid;
        inv_w_s[tid]   = (v < V_) ? g_inv_w[v] : 0.f;
    }

    uint32_t acc[4][4][2];  // fp16 accumulators (half2 pairs)
#pragma unroll
    for (int mf = 0; mf < 4; mf++)
#pragma unroll
        for (int nf = 0; nf < 4; nf++) {
            acc[mf][nf][0] = 0u;
            acc[mf][nf][1] = 0u;
        }

    const int KT = D_ / BK;  // 16
    for (int kt = 0; kt < KT; kt++) {
        asm volatile("cp.async.wait_group 1;\n" ::: "memory");
        __syncthreads();
        if (kt + 2 < KT) load_tiles(kt + 2, (kt + 2) % STAGES);
        else asm volatile("cp.async.commit_group;\n" ::: "memory");  // keep group count uniform

        int buf = kt % STAGES;
        uint32_t abase = as0 + buf * (A_STAGE * 2);
        uint32_t bbase = bs0 + buf * (B_STAGE * 2);

#pragma unroll
        for (int ks = 0; ks < 2; ks++) {
            uint32_t a[4][4];
#pragma unroll
            for (int mf = 0; mf < 4; mf++) {
                int row = wm * 64 + mf * 16 + (lane & 15);
                int col = ks * 16 + (lane >> 4) * 8;
                ldsm_x4(a[mf][0], a[mf][1], a[mf][2], a[mf][3],
                        abase + (row * A_PITCH + col) * 2);
            }
            uint32_t b[4][2];
#pragma unroll
            for (int ng = 0; ng < 2; ng++) {
                int krow = ks * 16 + (lane & 15);
                int ncol = wn * 32 + ng * 16 + (lane >> 4) * 8;
                uint32_t r0, r1, r2, r3;
                ldsm_x4_t(r0, r1, r2, r3, bbase + (krow * B_PITCH + ncol) * 2);
                b[ng * 2][0] = r0;      b[ng * 2][1] = r1;
                b[ng * 2 + 1][0] = r2;  b[ng * 2 + 1][1] = r3;
            }
#pragma unroll
            for (int mf = 0; mf < 4; mf++)
#pragma unroll
                for (int nf = 0; nf < 4; nf++)
                    mma16816_f16(acc[mf][nf], a[mf], b[nf]);
        }
    }
    __syncthreads();  // all compute done; rowsum_sm zeros visible

    // ---- fused ArcFace epilogue ----
#pragma unroll
    for (int mf = 0; mf < 4; mf++) {
        float rs0 = 0.f, rs1 = 0.f;
        int r0 = wm * 64 + mf * 16 + (lane >> 2);
        int r1 = r0 + 8;
#pragma unroll
        for (int nf = 0; nf < 4; nf++) {
            int cbase = wn * 32 + nf * 8 + (lane & 3) * 2;
            float2 v0 = __half22float2(*reinterpret_cast<__half2*>(&acc[mf][nf][0]));  // row r0
            float2 v1 = __half22float2(*reinterpret_cast<__half2*>(&acc[mf][nf][1]));  // row r1
            float d0[2] = {v0.x, v0.y};
            float d1[2] = {v1.x, v1.y};
#pragma unroll
            for (int j = 0; j < 2; j++) {
                int cc = cbase + j;
                int v = bn * BN + cc;
                if (v < V_) {
                    {
                        float cv = d0[j] * inv_x_s[r0] * inv_w_s[cc];
                        cv = fminf(fmaxf(cv, -1.f + EPS_CLIP), 1.f - EPS_CLIP);
                        float lg;
                        if (label_s[r0] == v) {
                            float s = sqrtf(fmaxf(1.f - cv * cv, 0.f));
                            lg = cv * MARGIN_COS - s * MARGIN_SIN;
                            g_label_logit[bm * BM + r0] = lg;
                        } else lg = cv;
                        rs0 += __expf(lg);
                    }
                    {
                        float cv = d1[j] * inv_x_s[r1] * inv_w_s[cc];
                        cv = fminf(fmaxf(cv, -1.f + EPS_CLIP), 1.f - EPS_CLIP);
                        float lg;
                        if (label_s[r1] == v) {
                            float s = sqrtf(fmaxf(1.f - cv * cv, 0.f));
                            lg = cv * MARGIN_COS - s * MARGIN_SIN;
                            g_label_logit[bm * BM + r1] = lg;
                        } else lg = cv;
                        rs1 += __expf(lg);
                    }
                }
            }
        }
        rs0 += __shfl_xor_sync(0xffffffffu, rs0, 1);
        rs0 += __shfl_xor_sync(0xffffffffu, rs0, 2);
        rs1 += __shfl_xor_sync(0xffffffffu, rs1, 1);
        rs1 += __shfl_xor_sync(0xffffffffu, rs1, 2);
        if ((lane & 3) == 0) {
            atomicAdd(&rowsum_sm[r0], rs0);
            atomicAdd(&rowsum_sm[r1], rs1);
        }
    }
    __syncthreads();
    if (tid < BM) atomicAdd(&g_sumexp[bm * BM + tid], rowsum_sm[tid]);
}

// ============================================================
// final: loss = mean_b( log(sumexp[b]) - label_logit[b] )
// ============================================================
__global__ void k_final(float* __restrict__ out) {
    int t = threadIdx.x;  // 1024
    float v = logf(g_sumexp[t]) - g_label_logit[t];
#pragma unroll
    for (int o = 16; o; o >>= 1) v += __shfl_xor_sync(0xffffffffu, v, o);
    __shared__ float ws[32];
    if ((t & 31) == 0) ws[t >> 5] = v;
    __syncthreads();
    if (t < 32) {
        float s = ws[t];
#pragma unroll
        for (int o = 16; o; o >>= 1) s += __shfl_xor_sync(0xffffffffu, s, o);
        if (t == 0) out[0] = s * (1.0f / (float)B_);
    }
}

// ============================================================
// Chunked prep_w on a forked stream, overlapped with GEMM chunks.
// Stream/event objects created once at first (uncaptured) call;
// inside capture only launches + event record/wait are issued.
// ============================================================
#define NCHUNK 4
#define BN_TILES 391            // ceil(100000 / 256)
#define BN_PER_CHUNK 98         // ceil(391 / 4)

extern "C" void kernel_launch(void* const* d_in, const int* in_sizes, int n_in,
                              void* d_out, int out_size) {
    const float* x = (const float*)d_in[0];
    const float* w = (const float*)d_in[1];
    const int*   labels_raw = (const int*)d_in[2];
    float* out = (float*)d_out;

    static bool init_done = false;
    static cudaStream_t s2;
    static cudaEvent_t e_fork, e_chunk[NCHUNK];
    if (!init_done) {
        cudaFuncSetAttribute(k_gemm, cudaFuncAttributeMaxDynamicSharedMemorySize, SMEM_DYN);
        cudaStreamCreateWithFlags(&s2, cudaStreamNonBlocking);
        cudaEventCreateWithFlags(&e_fork, cudaEventDisableTiming);
        for (int c = 0; c < NCHUNK; c++)
            cudaEventCreateWithFlags(&e_chunk[c], cudaEventDisableTiming);
        init_done = true;
    }

    // fork s2 off the main (capture) stream
    cudaEventRecord(e_fork, 0);
    cudaStreamWaitEvent(s2, e_fork, 0);

    // prep_w chunks on s2 (runs concurrently with labels/prep_x/gemm on stream 0)
    for (int c = 0; c < NCHUNK; c++) {
        int bn0 = c * BN_PER_CHUNK;
        int cnt = (BN_TILES - bn0 < BN_PER_CHUNK) ? (BN_TILES - bn0) : BN_PER_CHUNK;
        int vlo = bn0 * BN;
        int vhi = (bn0 + cnt) * BN;  if (vhi > V_) vhi = V_;
        int nblk = (vhi - vlo + 255) / 256;
        k_prep_w<<<nblk, 256, 0, s2>>>(w, vlo, vhi);
        cudaEventRecord(e_chunk[c], s2);
    }

    // main stream: small preps, then gemm chunks gated per-chunk
    k_labels<<<1, 1024>>>(labels_raw);
    k_prep_x<<<B_, 128>>>(x);
    for (int c = 0; c < NCHUNK; c++) {
        int bn0 = c * BN_PER_CHUNK;
        int cnt = (BN_TILES - bn0 < BN_PER_CHUNK) ? (BN_TILES - bn0) : BN_PER_CHUNK;
        cudaStreamWaitEvent(0, e_chunk[c], 0);
        dim3 grid(B_ / BM, cnt);
        k_gemm<<<grid, 512, SMEM_DYN>>>(bn0);
    }
    k_final<<<1, 1024>>>(out);
}

// round 14
// speedup vs baseline: 1.7048x; 1.1017x over previous
#include <cuda_runtime.h>
#include <cuda_fp16.h>
#include <cstdint>

#define B_  1024
#define D_  512
#define V_  100000

constexpr float MARGIN_COS = 0.9210609940028851f;  // cos(0.4)
constexpr float MARGIN_SIN = 0.3894183423086505f;  // sin(0.4)
constexpr float EPS_CLIP   = 1e-7f;

// ---- scratch (device globals: allocation-free per harness rules) ----
__device__ __align__(128) __half g_x16[B_ * D_];
__device__ __align__(128) __half g_w16[(size_t)D_ * V_];
__device__ float g_wpart[4][V_];   // partial column sum-of-squares (one per d-group)
__device__ float g_inv_x[B_];
__device__ float g_sumexp[B_];
__device__ float g_label_logit[B_];
__device__ int   g_labels[B_];

// ============================================================
// labels dtype detection (int64 vs int32) + normalization
// ============================================================
__global__ void k_labels(const int* __restrict__ raw) {
    __shared__ int nonzero;
    int t = threadIdx.x;  // 1024
    if (t == 0) nonzero = 0;
    __syncthreads();
    if (t < 512) {
        if (raw[2 * t + 1] != 0) atomicOr(&nonzero, 1);
    }
    __syncthreads();
    bool is64 = (nonzero == 0);
    g_labels[t] = is64 ? raw[2 * t] : raw[t];
}

// ============================================================
// x prep: fp16 convert + row inv-norms; zero g_sumexp
// ============================================================
__global__ void k_prep_x(const float* __restrict__ x) {
    int b = blockIdx.x;
    int t = threadIdx.x;  // 128
    float ss = 0.f;
#pragma unroll
    for (int i = 0; i < 4; i++) {
        int k = t + i * 128;
        float v = x[b * D_ + k];
        ss += v * v;
        g_x16[b * D_ + k] = __float2half(v);
    }
#pragma unroll
    for (int o = 16; o; o >>= 1) ss += __shfl_xor_sync(0xffffffffu, ss, o);
    __shared__ float ws[4];
    if ((t & 31) == 0) ws[t >> 5] = ss;
    __syncthreads();
    if (t == 0) {
        float s = ws[0] + ws[1] + ws[2] + ws[3];
        g_inv_x[b]  = 1.0f / fmaxf(sqrtf(s), 1e-12f);
        g_sumexp[b] = 0.f;
    }
}

// ============================================================
// w prep (chunked, 2D): fp16 convert + PARTIAL column sumsq
// grid = (ceil(cols/256), 4); block (dg) covers d in [dg*128, dg*128+128)
// 392 CTAs per chunk -> chip-saturating MLP
// ============================================================
__global__ void k_prep_w(const float* __restrict__ w, int vlo, int vhi) {
    int v = vlo + blockIdx.x * 256 + threadIdx.x;
    int dg = blockIdx.y;
    if (v >= vhi) return;
    float ss = 0.f;
    size_t idx = (size_t)(dg * 128) * V_ + v;
#pragma unroll 8
    for (int d = 0; d < 128; d++) {
        float val = w[idx];
        ss += val * val;
        g_w16[idx] = __float2half(val);
        idx += V_;
    }
    g_wpart[dg][v] = ss;
}

// ============================================================
// GEMM + fused ArcFace epilogue  (fp16 inputs, fp16 accum)
// CTA: BM=128 x BN=256, BK=32, 512 threads (2x8 warp grid, 64x32/warp)
// 2 CTAs/SM; 3-stage cp.async ring; mma.sync m16n8k16 f16
// ============================================================
#define BM 128
#define BN 256
#define BK 32
#define STAGES 3
#define A_PITCH 40    // 32 + 8 pad (80B rows; conflict-free ldmatrix)
#define B_PITCH 264   // 256 + 8 pad (528B rows; 528 mod 128 = 16 -> conflict-free)
#define A_STAGE (BM * A_PITCH)          // halves = 5120
#define B_STAGE (BK * B_PITCH)          // 8448
#define SMEM_DYN ((A_STAGE + B_STAGE) * STAGES * 2)  // 81408 bytes

__device__ __forceinline__ void cp_async16(uint32_t smem, const void* gmem, int sz) {
    asm volatile("cp.async.cg.shared.global [%0], [%1], 16, %2;\n"
                 :: "r"(smem), "l"(gmem), "r"(sz) : "memory");
}
__device__ __forceinline__ void ldsm_x4(uint32_t& r0, uint32_t& r1, uint32_t& r2, uint32_t& r3, uint32_t addr) {
    asm volatile("ldmatrix.sync.aligned.m8n8.x4.shared.b16 {%0,%1,%2,%3}, [%4];\n"
                 : "=r"(r0), "=r"(r1), "=r"(r2), "=r"(r3) : "r"(addr));
}
__device__ __forceinline__ void ldsm_x4_t(uint32_t& r0, uint32_t& r1, uint32_t& r2, uint32_t& r3, uint32_t addr) {
    asm volatile("ldmatrix.sync.aligned.m8n8.x4.trans.shared.b16 {%0,%1,%2,%3}, [%4];\n"
                 : "=r"(r0), "=r"(r1), "=r"(r2), "=r"(r3) : "r"(addr));
}
__device__ __forceinline__ void mma16816_f16(uint32_t* c, const uint32_t* a, const uint32_t* b) {
    asm volatile(
        "mma.sync.aligned.m16n8k16.row.col.f16.f16.f16.f16 "
        "{%0,%1}, {%2,%3,%4,%5}, {%6,%7}, {%0,%1};\n"
        : "+r"(c[0]), "+r"(c[1])
        : "r"(a[0]), "r"(a[1]), "r"(a[2]), "r"(a[3]), "r"(b[0]), "r"(b[1]));
}

__global__ __launch_bounds__(512, 2) void k_gemm(int bn0) {
    extern __shared__ __half smem_dyn[];
    __half* As = smem_dyn;                       // STAGES * A_STAGE
    __half* Bs = smem_dyn + STAGES * A_STAGE;    // STAGES * B_STAGE
    __shared__ float rowsum_sm[BM];
    __shared__ float inv_x_s[BM];
    __shared__ float inv_w_s[BN];
    __shared__ int   label_s[BM];

    const int bm = blockIdx.x;          // M-tile (fast index -> same-w CTAs adjacent)
    const int bn = blockIdx.y + bn0;    // V-slice (chunk offset)
    const int tid = threadIdx.x;
    const int warp = tid >> 5, lane = tid & 31;
    const int wm = warp & 1;     // 2 warps over M (64 rows each)
    const int wn = warp >> 1;    // 8 warps over N (32 cols each)

    const uint32_t as0 = (uint32_t)__cvta_generic_to_shared(As);
    const uint32_t bs0 = (uint32_t)__cvta_generic_to_shared(Bs);

    // 512 threads: A 8KB -> 1 cp16/thread; B 16KB -> 2 cp16/thread
    auto load_tiles = [&](int kt, int buf) {
        {
            int row  = tid >> 2;             // 0..127
            int koff = (tid & 3) * 8;        // 0,8,16,24
            const __half* gp = &g_x16[(bm * BM + row) * D_ + kt * BK + koff];
            cp_async16(as0 + (buf * A_STAGE + row * A_PITCH + koff) * 2, gp, 16);
        }
#pragma unroll
        for (int i = 0; i < 2; i++) {
            int c = tid + i * 512;           // 0..1023
            int drow = c >> 5;               // 0..31
            int voff = (c & 31) * 8;         // 0..248
            int v = bn * BN + voff;
            const __half* gp = &g_w16[(size_t)(kt * BK + drow) * V_ + v];
            cp_async16(bs0 + (buf * B_STAGE + drow * B_PITCH + voff) * 2, gp, (v < V_) ? 16 : 0);
        }
        asm volatile("cp.async.commit_group;\n" ::: "memory");
    };

    load_tiles(0, 0);
    load_tiles(1, 1);

    if (tid < BM) {
        inv_x_s[tid]   = g_inv_x[bm * BM + tid];
        label_s[tid]   = g_labels[bm * BM + tid];
        rowsum_sm[tid] = 0.f;
    }
    if (tid < BN) {
        int v = bn * BN + tid;
        float s = 0.f;
        if (v < V_)
            s = g_wpart[0][v] + g_wpart[1][v] + g_wpart[2][v] + g_wpart[3][v];
        inv_w_s[tid] = (v < V_) ? 1.0f / fmaxf(sqrtf(s), 1e-12f) : 0.f;
    }

    uint32_t acc[4][4][2];  // fp16 accumulators (half2 pairs)
#pragma unroll
    for (int mf = 0; mf < 4; mf++)
#pragma unroll
        for (int nf = 0; nf < 4; nf++) {
            acc[mf][nf][0] = 0u;
            acc[mf][nf][1] = 0u;
        }

    const int KT = D_ / BK;  // 16
    for (int kt = 0; kt < KT; kt++) {
        asm volatile("cp.async.wait_group 1;\n" ::: "memory");
        __syncthreads();
        if (kt + 2 < KT) load_tiles(kt + 2, (kt + 2) % STAGES);
        else asm volatile("cp.async.commit_group;\n" ::: "memory");  // keep group count uniform

        int buf = kt % STAGES;
        uint32_t abase = as0 + buf * (A_STAGE * 2);
        uint32_t bbase = bs0 + buf * (B_STAGE * 2);

#pragma unroll
        for (int ks = 0; ks < 2; ks++) {
            uint32_t a[4][4];
#pragma unroll
            for (int mf = 0; mf < 4; mf++) {
                int row = wm * 64 + mf * 16 + (lane & 15);
                int col = ks * 16 + (lane >> 4) * 8;
                ldsm_x4(a[mf][0], a[mf][1], a[mf][2], a[mf][3],
                        abase + (row * A_PITCH + col) * 2);
            }
            uint32_t b[4][2];
#pragma unroll
            for (int ng = 0; ng < 2; ng++) {
                int krow = ks * 16 + (lane & 15);
                int ncol = wn * 32 + ng * 16 + (lane >> 4) * 8;
                uint32_t r0, r1, r2, r3;
                ldsm_x4_t(r0, r1, r2, r3, bbase + (krow * B_PITCH + ncol) * 2);
                b[ng * 2][0] = r0;      b[ng * 2][1] = r1;
                b[ng * 2 + 1][0] = r2;  b[ng * 2 + 1][1] = r3;
            }
#pragma unroll
            for (int mf = 0; mf < 4; mf++)
#pragma unroll
                for (int nf = 0; nf < 4; nf++)
                    mma16816_f16(acc[mf][nf], a[mf], b[nf]);
        }
    }
    __syncthreads();  // all compute done; rowsum_sm zeros visible

    // ---- fused ArcFace epilogue ----
#pragma unroll
    for (int mf = 0; mf < 4; mf++) {
        float rs0 = 0.f, rs1 = 0.f;
        int r0 = wm * 64 + mf * 16 + (lane >> 2);
        int r1 = r0 + 8;
#pragma unroll
        for (int nf = 0; nf < 4; nf++) {
            int cbase = wn * 32 + nf * 8 + (lane & 3) * 2;
            float2 v0 = __half22float2(*reinterpret_cast<__half2*>(&acc[mf][nf][0]));  // row r0
            float2 v1 = __half22float2(*reinterpret_cast<__half2*>(&acc[mf][nf][1]));  // row r1
            float d0[2] = {v0.x, v0.y};
            float d1[2] = {v1.x, v1.y};
#pragma unroll
            for (int j = 0; j < 2; j++) {
                int cc = cbase + j;
                int v = bn * BN + cc;
                if (v < V_) {
                    {
                        float cv = d0[j] * inv_x_s[r0] * inv_w_s[cc];
                        cv = fminf(fmaxf(cv, -1.f + EPS_CLIP), 1.f - EPS_CLIP);
                        float lg;
                        if (label_s[r0] == v) {
                            float s = sqrtf(fmaxf(1.f - cv * cv, 0.f));
                            lg = cv * MARGIN_COS - s * MARGIN_SIN;
                            g_label_logit[bm * BM + r0] = lg;
                        } else lg = cv;
                        rs0 += __expf(lg);
                    }
                    {
                        float cv = d1[j] * inv_x_s[r1] * inv_w_s[cc];
                        cv = fminf(fmaxf(cv, -1.f + EPS_CLIP), 1.f - EPS_CLIP);
                        float lg;
                        if (label_s[r1] == v) {
                            float s = sqrtf(fmaxf(1.f - cv * cv, 0.f));
                            lg = cv * MARGIN_COS - s * MARGIN_SIN;
                            g_label_logit[bm * BM + r1] = lg;
                        } else lg = cv;
                        rs1 += __expf(lg);
                    }
                }
            }
        }
        rs0 += __shfl_xor_sync(0xffffffffu, rs0, 1);
        rs0 += __shfl_xor_sync(0xffffffffu, rs0, 2);
        rs1 += __shfl_xor_sync(0xffffffffu, rs1, 1);
        rs1 += __shfl_xor_sync(0xffffffffu, rs1, 2);
        if ((lane & 3) == 0) {
            atomicAdd(&rowsum_sm[r0], rs0);
            atomicAdd(&rowsum_sm[r1], rs1);
        }
    }
    __syncthreads();
    if (tid < BM) atomicAdd(&g_sumexp[bm * BM + tid], rowsum_sm[tid]);
}

// ============================================================
// final: loss = mean_b( log(sumexp[b]) - label_logit[b] )
// ============================================================
__global__ void k_final(float* __restrict__ out) {
    int t = threadIdx.x;  // 1024
    float v = logf(g_sumexp[t]) - g_label_logit[t];
#pragma unroll
    for (int o = 16; o; o >>= 1) v += __shfl_xor_sync(0xffffffffu, v, o);
    __shared__ float ws[32];
    if ((t & 31) == 0) ws[t >> 5] = v;
    __syncthreads();
    if (t < 32) {
        float s = ws[t];
#pragma unroll
        for (int o = 16; o; o >>= 1) s += __shfl_xor_sync(0xffffffffu, s, o);
        if (t == 0) out[0] = s * (1.0f / (float)B_);
    }
}

// ============================================================
// Chunked prep_w (2D grid, chip-saturating) on a forked stream,
// overlapped with per-chunk-gated GEMM on the main stream.
// ============================================================
#define NCHUNK 4
#define BN_TILES 391            // ceil(100000 / 256)
#define BN_PER_CHUNK 98         // ceil(391 / 4)

extern "C" void kernel_launch(void* const* d_in, const int* in_sizes, int n_in,
                              void* d_out, int out_size) {
    const float* x = (const float*)d_in[0];
    const float* w = (const float*)d_in[1];
    const int*   labels_raw = (const int*)d_in[2];
    float* out = (float*)d_out;

    static bool init_done = false;
    static cudaStream_t s2;
    static cudaEvent_t e_fork, e_chunk[NCHUNK];
    if (!init_done) {
        cudaFuncSetAttribute(k_gemm, cudaFuncAttributeMaxDynamicSharedMemorySize, SMEM_DYN);
        cudaStreamCreateWithFlags(&s2, cudaStreamNonBlocking);
        cudaEventCreateWithFlags(&e_fork, cudaEventDisableTiming);
        for (int c = 0; c < NCHUNK; c++)
            cudaEventCreateWithFlags(&e_chunk[c], cudaEventDisableTiming);
        init_done = true;
    }

    // fork s2 off the main (capture) stream
    cudaEventRecord(e_fork, 0);
    cudaStreamWaitEvent(s2, e_fork, 0);

    // prep_w chunks on s2: 2D grids (v-blocks x 4 d-groups) = ~392 CTAs each
    for (int c = 0; c < NCHUNK; c++) {
        int bn0 = c * BN_PER_CHUNK;
        int cnt = (BN_TILES - bn0 < BN_PER_CHUNK) ? (BN_TILES - bn0) : BN_PER_CHUNK;
        int vlo = bn0 * BN;
        int vhi = (bn0 + cnt) * BN;  if (vhi > V_) vhi = V_;
        dim3 pgrid((vhi - vlo + 255) / 256, 4);
        k_prep_w<<<pgrid, 256, 0, s2>>>(w, vlo, vhi);
        cudaEventRecord(e_chunk[c], s2);
    }

    // main stream: small preps, then gemm chunks gated per-chunk
    k_labels<<<1, 1024>>>(labels_raw);
    k_prep_x<<<B_, 128>>>(x);
    for (int c = 0; c < NCHUNK; c++) {
        int bn0 = c * BN_PER_CHUNK;
        int cnt = (BN_TILES - bn0 < BN_PER_CHUNK) ? (BN_TILES - bn0) : BN_PER_CHUNK;
        cudaStreamWaitEvent(0, e_chunk[c], 0);
        dim3 grid(B_ / BM, cnt);
        k_gemm<<<grid, 512, SMEM_DYN>>>(bn0);
    }
    k_final<<<1, 1024>>>(out);
}

// round 15
// speedup vs baseline: 1.9480x; 1.1427x over previous
#include <cuda_runtime.h>
#include <cuda_fp16.h>
#include <cstdint>

#define B_  1024
#define D_  512
#define V_  100000

constexpr float MARGIN_COS = 0.9210609940028851f;  // cos(0.4)
constexpr float MARGIN_SIN = 0.3894183423086505f;  // sin(0.4)
constexpr float EPS_CLIP   = 1e-7f;

// ---- scratch (device globals: allocation-free per harness rules) ----
__device__ __align__(128) __half g_x16[B_ * D_];
__device__ __align__(128) __half g_w16[(size_t)D_ * V_];
__device__ float g_wpart[4][V_];   // partial column sum-of-squares (one per d-group)
__device__ float g_inv_x[B_];
__device__ float g_sumexp[B_];
__device__ float g_label_logit[B_];
__device__ int   g_labels[B_];

// ============================================================
// x prep: float4 loads, fp16 convert + row inv-norms; zero g_sumexp.
// Block 0 additionally normalizes labels (int64 vs int32 detection).
// ============================================================
__global__ void k_prep_x(const float* __restrict__ x, const int* __restrict__ raw) {
    int b = blockIdx.x;
    int t = threadIdx.x;  // 128

    if (b == 0) {
        // labels: detect dtype by probing odd int32 words of first 512 entries
        __shared__ int nonzero;
        if (t == 0) nonzero = 0;
        __syncthreads();
        for (int i = t; i < 512; i += 128)
            if (raw[2 * i + 1] != 0) atomicOr(&nonzero, 1);
        __syncthreads();
        bool is64 = (nonzero == 0);
        for (int i = t; i < B_; i += 128)
            g_labels[i] = is64 ? raw[2 * i] : raw[i];
    }

    float4 v4 = *reinterpret_cast<const float4*>(&x[b * D_ + t * 4]);
    float ss = v4.x * v4.x + v4.y * v4.y + v4.z * v4.z + v4.w * v4.w;
    __half2 h01 = __floats2half2_rn(v4.x, v4.y);
    __half2 h23 = __floats2half2_rn(v4.z, v4.w);
    uint2 packed = make_uint2(*reinterpret_cast<uint32_t*>(&h01),
                              *reinterpret_cast<uint32_t*>(&h23));
    *reinterpret_cast<uint2*>(&g_x16[b * D_ + t * 4]) = packed;

#pragma unroll
    for (int o = 16; o; o >>= 1) ss += __shfl_xor_sync(0xffffffffu, ss, o);
    __shared__ float ws[4];
    if ((t & 31) == 0) ws[t >> 5] = ss;
    __syncthreads();
    if (t == 0) {
        float s = ws[0] + ws[1] + ws[2] + ws[3];
        g_inv_x[b]  = 1.0f / fmaxf(sqrtf(s), 1e-12f);
        g_sumexp[b] = 0.f;
    }
}

// ============================================================
// w prep (2D, chip-saturating): fp16 convert + PARTIAL column sumsq
// grid = (ceil(V/256), 4) = 1564 CTAs; dg covers d in [dg*128, dg*128+128)
// ============================================================
__global__ void k_prep_w(const float* __restrict__ w) {
    int v = blockIdx.x * 256 + threadIdx.x;
    int dg = blockIdx.y;
    if (v >= V_) return;
    float ss = 0.f;
    size_t idx = (size_t)(dg * 128) * V_ + v;
#pragma unroll 8
    for (int d = 0; d < 128; d++) {
        float val = w[idx];
        ss += val * val;
        g_w16[idx] = __float2half(val);
        idx += V_;
    }
    g_wpart[dg][v] = ss;
}

// ============================================================
// GEMM + fused ArcFace epilogue  (fp16 inputs, fp16 accum)
// CTA: BM=128 x BN=256, BK=32, 512 threads (2x8 warp grid, 64x32/warp)
// 2 CTAs/SM; 3-stage cp.async ring; mma.sync m16n8k16 f16
// ============================================================
#define BM 128
#define BN 256
#define BK 32
#define STAGES 3
#define A_PITCH 40    // 32 + 8 pad (80B rows; conflict-free ldmatrix)
#define B_PITCH 264   // 256 + 8 pad (528B rows; 528 mod 128 = 16 -> conflict-free)
#define A_STAGE (BM * A_PITCH)          // halves = 5120
#define B_STAGE (BK * B_PITCH)          // 8448
#define SMEM_DYN ((A_STAGE + B_STAGE) * STAGES * 2)  // 81408 bytes

__device__ __forceinline__ void cp_async16(uint32_t smem, const void* gmem, int sz) {
    asm volatile("cp.async.cg.shared.global [%0], [%1], 16, %2;\n"
                 :: "r"(smem), "l"(gmem), "r"(sz) : "memory");
}
__device__ __forceinline__ void ldsm_x4(uint32_t& r0, uint32_t& r1, uint32_t& r2, uint32_t& r3, uint32_t addr) {
    asm volatile("ldmatrix.sync.aligned.m8n8.x4.shared.b16 {%0,%1,%2,%3}, [%4];\n"
                 : "=r"(r0), "=r"(r1), "=r"(r2), "=r"(r3) : "r"(addr));
}
__device__ __forceinline__ void ldsm_x4_t(uint32_t& r0, uint32_t& r1, uint32_t& r2, uint32_t& r3, uint32_t addr) {
    asm volatile("ldmatrix.sync.aligned.m8n8.x4.trans.shared.b16 {%0,%1,%2,%3}, [%4];\n"
                 : "=r"(r0), "=r"(r1), "=r"(r2), "=r"(r3) : "r"(addr));
}
__device__ __forceinline__ void mma16816_f16(uint32_t* c, const uint32_t* a, const uint32_t* b) {
    asm volatile(
        "mma.sync.aligned.m16n8k16.row.col.f16.f16.f16.f16 "
        "{%0,%1}, {%2,%3,%4,%5}, {%6,%7}, {%0,%1};\n"
        : "+r"(c[0]), "+r"(c[1])
        : "r"(a[0]), "r"(a[1]), "r"(a[2]), "r"(a[3]), "r"(b[0]), "r"(b[1]));
}

__global__ __launch_bounds__(512, 2) void k_gemm() {
    extern __shared__ __half smem_dyn[];
    __half* As = smem_dyn;                       // STAGES * A_STAGE
    __half* Bs = smem_dyn + STAGES * A_STAGE;    // STAGES * B_STAGE
    __shared__ float rowsum_sm[BM];
    __shared__ float inv_x_s[BM];
    __shared__ float inv_w_s[BN];
    __shared__ int   label_s[BM];

    const int bm = blockIdx.x;   // M-tile (fast index -> same-w CTAs adjacent)
    const int bn = blockIdx.y;   // V-slice
    const int tid = threadIdx.x;
    const int warp = tid >> 5, lane = tid & 31;
    const int wm = warp & 1;     // 2 warps over M (64 rows each)
    const int wn = warp >> 1;    // 8 warps over N (32 cols each)

    const uint32_t as0 = (uint32_t)__cvta_generic_to_shared(As);
    const uint32_t bs0 = (uint32_t)__cvta_generic_to_shared(Bs);

    // 512 threads: A 8KB -> 1 cp16/thread; B 16KB -> 2 cp16/thread
    auto load_tiles = [&](int kt, int buf) {
        {
            int row  = tid >> 2;             // 0..127
            int koff = (tid & 3) * 8;        // 0,8,16,24
            const __half* gp = &g_x16[(bm * BM + row) * D_ + kt * BK + koff];
            cp_async16(as0 + (buf * A_STAGE + row * A_PITCH + koff) * 2, gp, 16);
        }
#pragma unroll
        for (int i = 0; i < 2; i++) {
            int c = tid + i * 512;           // 0..1023
            int drow = c >> 5;               // 0..31
            int voff = (c & 31) * 8;         // 0..248
            int v = bn * BN + voff;
            const __half* gp = &g_w16[(size_t)(kt * BK + drow) * V_ + v];
            cp_async16(bs0 + (buf * B_STAGE + drow * B_PITCH + voff) * 2, gp, (v < V_) ? 16 : 0);
        }
        asm volatile("cp.async.commit_group;\n" ::: "memory");
    };

    load_tiles(0, 0);
    load_tiles(1, 1);

    if (tid < BM) {
        inv_x_s[tid]   = g_inv_x[bm * BM + tid];
        label_s[tid]   = g_labels[bm * BM + tid];
        rowsum_sm[tid] = 0.f;
    }
    if (tid < BN) {
        int v = bn * BN + tid;
        float s = 0.f;
        if (v < V_)
            s = g_wpart[0][v] + g_wpart[1][v] + g_wpart[2][v] + g_wpart[3][v];
        inv_w_s[tid] = (v < V_) ? 1.0f / fmaxf(sqrtf(s), 1e-12f) : 0.f;
    }

    uint32_t acc[4][4][2];  // fp16 accumulators (half2 pairs)
#pragma unroll
    for (int mf = 0; mf < 4; mf++)
#pragma unroll
        for (int nf = 0; nf < 4; nf++) {
            acc[mf][nf][0] = 0u;
            acc[mf][nf][1] = 0u;
        }

    const int KT = D_ / BK;  // 16
    for (int kt = 0; kt < KT; kt++) {
        asm volatile("cp.async.wait_group 1;\n" ::: "memory");
        __syncthreads();
        if (kt + 2 < KT) load_tiles(kt + 2, (kt + 2) % STAGES);
        else asm volatile("cp.async.commit_group;\n" ::: "memory");  // keep group count uniform

        int buf = kt % STAGES;
        uint32_t abase = as0 + buf * (A_STAGE * 2);
        uint32_t bbase = bs0 + buf * (B_STAGE * 2);

#pragma unroll
        for (int ks = 0; ks < 2; ks++) {
            uint32_t a[4][4];
#pragma unroll
            for (int mf = 0; mf < 4; mf++) {
                int row = wm * 64 + mf * 16 + (lane & 15);
                int col = ks * 16 + (lane >> 4) * 8;
                ldsm_x4(a[mf][0], a[mf][1], a[mf][2], a[mf][3],
                        abase + (row * A_PITCH + col) * 2);
            }
            uint32_t b[4][2];
#pragma unroll
            for (int ng = 0; ng < 2; ng++) {
                int krow = ks * 16 + (lane & 15);
                int ncol = wn * 32 + ng * 16 + (lane >> 4) * 8;
                uint32_t r0, r1, r2, r3;
                ldsm_x4_t(r0, r1, r2, r3, bbase + (krow * B_PITCH + ncol) * 2);
                b[ng * 2][0] = r0;      b[ng * 2][1] = r1;
                b[ng * 2 + 1][0] = r2;  b[ng * 2 + 1][1] = r3;
            }
#pragma unroll
            for (int mf = 0; mf < 4; mf++)
#pragma unroll
                for (int nf = 0; nf < 4; nf++)
                    mma16816_f16(acc[mf][nf], a[mf], b[nf]);
        }
    }
    __syncthreads();  // all compute done; rowsum_sm zeros visible

    // ---- fused ArcFace epilogue ----
#pragma unroll
    for (int mf = 0; mf < 4; mf++) {
        float rs0 = 0.f, rs1 = 0.f;
        int r0 = wm * 64 + mf * 16 + (lane >> 2);
        int r1 = r0 + 8;
#pragma unroll
        for (int nf = 0; nf < 4; nf++) {
            int cbase = wn * 32 + nf * 8 + (lane & 3) * 2;
            float2 v0 = __half22float2(*reinterpret_cast<__half2*>(&acc[mf][nf][0]));  // row r0
            float2 v1 = __half22float2(*reinterpret_cast<__half2*>(&acc[mf][nf][1]));  // row r1
            float d0[2] = {v0.x, v0.y};
            float d1[2] = {v1.x, v1.y};
#pragma unroll
            for (int j = 0; j < 2; j++) {
                int cc = cbase + j;
                int v = bn * BN + cc;
                if (v < V_) {
                    {
                        float cv = d0[j] * inv_x_s[r0] * inv_w_s[cc];
                        cv = fminf(fmaxf(cv, -1.f + EPS_CLIP), 1.f - EPS_CLIP);
                        float lg;
                        if (label_s[r0] == v) {
                            float s = sqrtf(fmaxf(1.f - cv * cv, 0.f));
                            lg = cv * MARGIN_COS - s * MARGIN_SIN;
                            g_label_logit[bm * BM + r0] = lg;
                        } else lg = cv;
                        rs0 += __expf(lg);
                    }
                    {
                        float cv = d1[j] * inv_x_s[r1] * inv_w_s[cc];
                        cv = fminf(fmaxf(cv, -1.f + EPS_CLIP), 1.f - EPS_CLIP);
                        float lg;
                        if (label_s[r1] == v) {
                            float s = sqrtf(fmaxf(1.f - cv * cv, 0.f));
                            lg = cv * MARGIN_COS - s * MARGIN_SIN;
                            g_label_logit[bm * BM + r1] = lg;
                        } else lg = cv;
                        rs1 += __expf(lg);
                    }
                }
            }
        }
        rs0 += __shfl_xor_sync(0xffffffffu, rs0, 1);
        rs0 += __shfl_xor_sync(0xffffffffu, rs0, 2);
        rs1 += __shfl_xor_sync(0xffffffffu, rs1, 1);
        rs1 += __shfl_xor_sync(0xffffffffu, rs1, 2);
        if ((lane & 3) == 0) {
            atomicAdd(&rowsum_sm[r0], rs0);
            atomicAdd(&rowsum_sm[r1], rs1);
        }
    }
    __syncthreads();
    if (tid < BM) atomicAdd(&g_sumexp[bm * BM + tid], rowsum_sm[tid]);
}

// ============================================================
// final: loss = mean_b( log(sumexp[b]) - label_logit[b] )
// ============================================================
__global__ void k_final(float* __restrict__ out) {
    int t = threadIdx.x;  // 1024
    float v = logf(g_sumexp[t]) - g_label_logit[t];
#pragma unroll
    for (int o = 16; o; o >>= 1) v += __shfl_xor_sync(0xffffffffu, v, o);
    __shared__ float ws[32];
    if ((t & 31) == 0) ws[t >> 5] = v;
    __syncthreads();
    if (t < 32) {
        float s = ws[t];
#pragma unroll
        for (int o = 16; o; o >>= 1) s += __shfl_xor_sync(0xffffffffu, s, o);
        if (t == 0) out[0] = s * (1.0f / (float)B_);
    }
}

// ============================================================
extern "C" void kernel_launch(void* const* d_in, const int* in_sizes, int n_in,
                              void* d_out, int out_size) {
    const float* x = (const float*)d_in[0];
    const float* w = (const float*)d_in[1];
    const int*   labels_raw = (const int*)d_in[2];
    float* out = (float*)d_out;

    static bool attr_set = false;
    if (!attr_set) {
        cudaFuncSetAttribute(k_gemm, cudaFuncAttributeMaxDynamicSharedMemorySize, SMEM_DYN);
        attr_set = true;
    }

    dim3 pgrid((V_ + 255) / 256, 4);   // 1564 CTAs, chip-saturating
    k_prep_w<<<pgrid, 256>>>(w);
    k_prep_x<<<B_, 128>>>(x, labels_raw);
    dim3 grid(B_ / BM, (V_ + BN - 1) / BN);  // (8, 391), single tail wave
    k_gemm<<<grid, 512, SMEM_DYN>>>();
    k_final<<<1, 1024>>>(out);
}